// round 4
// baseline (speedup 1.0000x reference)
#include <cuda_runtime.h>
#include <cuda_bf16.h>
#include <cstdint>

// Problem constants
#define B_   16
#define NA_  2048
#define NB_  2048
#define D_   512
#define M_   (B_ * NA_)      // 32768 tokens
#define TOPK_ 4

// Scratch (device globals: allocation-free per harness rules)
__device__ float    g_Pa[M_ * D_];            // feats_a @ W2 + bias     (64 MB)
__device__ float    g_Pb[M_ * D_];            // feats_b @ (W1 - W2)     (64 MB)
__device__ unsigned g_topk[M_ * TOPK_];       // final packed keys
__device__ uint4    g_part[M_ * 4];           // partial top-4 per NB-split (2 MB)
__device__ __nv_bfloat16 g_Bhi[2][D_ * D_];   // [mode][k*512+n]  hi part
__device__ __nv_bfloat16 g_Blo[2][D_ * D_];   // [mode][k*512+n]  lo part
__device__ __nv_bfloat16 g_Ahi[M_ * D_];      // current A operand, hi (32 MB)
__device__ __nv_bfloat16 g_Alo[M_ * D_];      // current A operand, lo (32 MB)

// ===========================================================================
// PTX helpers (baseline PTX only — compiles under compute_103)
// ===========================================================================
__device__ __forceinline__ uint32_t smem_u32(const void* p) {
    uint32_t a;
    asm("{ .reg .u64 t; cvta.to.shared.u64 t, %1; cvt.u32.u64 %0, t; }"
        : "=r"(a) : "l"(p));
    return a;
}
__device__ __forceinline__ void ldsm4(uint32_t addr, uint32_t* r) {
    asm volatile("ldmatrix.sync.aligned.m8n8.x4.shared.b16 {%0,%1,%2,%3}, [%4];"
                 : "=r"(r[0]), "=r"(r[1]), "=r"(r[2]), "=r"(r[3]) : "r"(addr));
}
__device__ __forceinline__ void ldsm4t(uint32_t addr, uint32_t* r) {
    asm volatile("ldmatrix.sync.aligned.m8n8.x4.trans.shared.b16 {%0,%1,%2,%3}, [%4];"
                 : "=r"(r[0]), "=r"(r[1]), "=r"(r[2]), "=r"(r[3]) : "r"(addr));
}
__device__ __forceinline__ void mma16816(float* c, const uint32_t* a, const uint32_t* b) {
    asm volatile(
        "mma.sync.aligned.m16n8k16.row.col.f32.bf16.bf16.f32 "
        "{%0,%1,%2,%3}, {%4,%5,%6,%7}, {%8,%9}, {%0,%1,%2,%3};"
        : "+f"(c[0]), "+f"(c[1]), "+f"(c[2]), "+f"(c[3])
        : "r"(a[0]), "r"(a[1]), "r"(a[2]), "r"(a[3]), "r"(b[0]), "r"(b[1]));
}
__device__ __forceinline__ void cp16(uint32_t s, const void* g) {
    asm volatile("cp.async.cg.shared.global [%0], [%1], 16;" :: "r"(s), "l"(g));
}
#define CP_COMMIT() asm volatile("cp.async.commit_group;" ::: "memory")
#define CP_WAIT2()  asm volatile("cp.async.wait_group 2;"  ::: "memory")

// ===========================================================================
// Kernel 1: prep — bf16 hi/lo split of W2 and (W1 - W2), natural [k][n] layout.
// ===========================================================================
__global__ void prep_kernel(const float* __restrict__ W) {
    int idx = blockIdx.x * blockDim.x + threadIdx.x;   // k*512 + n
    float w1 = W[idx];
    float w2 = W[idx + 512 * 512];
    float v0 = w2;
    float v1 = w1 - w2;
    __nv_bfloat16 h0 = __float2bfloat16(v0);
    __nv_bfloat16 l0 = __float2bfloat16(v0 - __bfloat162float(h0));
    __nv_bfloat16 h1 = __float2bfloat16(v1);
    __nv_bfloat16 l1 = __float2bfloat16(v1 - __bfloat162float(h1));
    g_Bhi[0][idx] = h0;  g_Blo[0][idx] = l0;
    g_Bhi[1][idx] = h1;  g_Blo[1][idx] = l1;
}

// ===========================================================================
// Kernel 1b: conv — fp32 feats -> bf16 hi/lo (streaming, memory-bound).
// ===========================================================================
__global__ void __launch_bounds__(256)
conv_kernel(const float* __restrict__ src) {
    int idx = blockIdx.x * blockDim.x + threadIdx.x;   // float4 index
    float4 v = ((const float4*)src)[idx];
    __nv_bfloat16 hx = __float2bfloat16(v.x);
    __nv_bfloat16 hy = __float2bfloat16(v.y);
    __nv_bfloat16 hz = __float2bfloat16(v.z);
    __nv_bfloat16 hw = __float2bfloat16(v.w);
    __nv_bfloat16 lx = __float2bfloat16(v.x - __bfloat162float(hx));
    __nv_bfloat16 ly = __float2bfloat16(v.y - __bfloat162float(hy));
    __nv_bfloat16 lz = __float2bfloat16(v.z - __bfloat162float(hz));
    __nv_bfloat16 lw = __float2bfloat16(v.w - __bfloat162float(hw));
    __nv_bfloat162 hp0(hx, hy), hp1(hz, hw), lp0(lx, ly), lp1(lz, lw);
    uint2 h2, l2;
    h2.x = *(const uint32_t*)&hp0;  h2.y = *(const uint32_t*)&hp1;
    l2.x = *(const uint32_t*)&lp0;  l2.y = *(const uint32_t*)&lp1;
    ((uint2*)g_Ahi)[idx] = h2;
    ((uint2*)g_Alo)[idx] = l2;
}

// ===========================================================================
// Kernel 2/3: bf16-split tensor-core GEMM, C(M x 512) = A @ Bm + bias
// CTA 128x128, 8 warps (2x4), warp 64x32. K stages of 32, 4-stage cp.async.
// 3 passes: Ah*Bh + Ah*Bl + Al*Bh
// ===========================================================================
#define A_ROW_B  80                       // bytes per A smem row (32 bf16 + pad)
#define B_ROW_B  272                      // bytes per B smem row (128 bf16 + pad)
#define A_PART   (128 * A_ROW_B)          // 10240 B
#define B_PART   (32 * B_ROW_B)           // 8704 B
#define OFF_AH   0
#define OFF_AL   A_PART
#define OFF_BH   (2 * A_PART)
#define OFF_BL   (2 * A_PART + B_PART)
#define BUF_SZ   (2 * A_PART + 2 * B_PART)   // 37888 B
#define NSTAGE   4
#define GEMM_SMEM (NSTAGE * BUF_SZ)          // 151552 B

template <int MODE>
__global__ void __launch_bounds__(256, 1)
mma_gemm(const float* __restrict__ bias) {
    extern __shared__ char smem[];
    const uint32_t sb = smem_u32(smem);

    const int tid  = threadIdx.x;
    const int wid  = tid >> 5;
    const int lane = tid & 31;
    const int wm   = wid & 1;
    const int wn   = wid >> 1;
    const int bn   = blockIdx.x;     // 0..3
    const int bm   = blockIdx.y;     // 0..255

    const __nv_bfloat16* Bh = g_Bhi[MODE];
    const __nv_bfloat16* Bl = g_Blo[MODE];
    float* C = (MODE == 0) ? g_Pa : g_Pb;
    const int nb = bn * 128;
    const size_t abase = (size_t)bm * 128;

    // cp.async index precompute (8x 16B chunks per thread per stage)
    const int a_id0 = tid * 2;
    const int a_row0 = a_id0 >> 2, a_c0 = (a_id0 & 3);
    const int a_row1 = (a_id0 + 1) >> 2, a_c1 = ((a_id0 + 1) & 3);
    const int b_br0 = a_id0 >> 4, b_bc0 = (a_id0 & 15) * 8;
    const int b_br1 = (a_id0 + 1) >> 4, b_bc1 = ((a_id0 + 1) & 15) * 8;

    auto issue_stage = [&](int s) {
        if (s < 16) {
            const uint32_t bp = sb + (s & (NSTAGE - 1)) * BUF_SZ;
            const int k0 = s * 32;
            cp16(bp + OFF_AH + a_row0 * A_ROW_B + a_c0 * 16,
                 g_Ahi + (abase + a_row0) * 512 + k0 + a_c0 * 8);
            cp16(bp + OFF_AL + a_row0 * A_ROW_B + a_c0 * 16,
                 g_Alo + (abase + a_row0) * 512 + k0 + a_c0 * 8);
            cp16(bp + OFF_AH + a_row1 * A_ROW_B + a_c1 * 16,
                 g_Ahi + (abase + a_row1) * 512 + k0 + a_c1 * 8);
            cp16(bp + OFF_AL + a_row1 * A_ROW_B + a_c1 * 16,
                 g_Alo + (abase + a_row1) * 512 + k0 + a_c1 * 8);
            cp16(bp + OFF_BH + b_br0 * B_ROW_B + b_bc0 * 2,
                 Bh + (size_t)(k0 + b_br0) * 512 + nb + b_bc0);
            cp16(bp + OFF_BL + b_br0 * B_ROW_B + b_bc0 * 2,
                 Bl + (size_t)(k0 + b_br0) * 512 + nb + b_bc0);
            cp16(bp + OFF_BH + b_br1 * B_ROW_B + b_bc1 * 2,
                 Bh + (size_t)(k0 + b_br1) * 512 + nb + b_bc1);
            cp16(bp + OFF_BL + b_br1 * B_ROW_B + b_bc1 * 2,
                 Bl + (size_t)(k0 + b_br1) * 512 + nb + b_bc1);
        }
        CP_COMMIT();   // empty group when s >= 16 keeps FIFO accounting uniform
    };

    // ldmatrix lane byte offsets
    const int r = lane & 7, q = lane >> 3;
    const uint32_t a_lane = (uint32_t)(((q & 1) * 8 + r) * A_ROW_B + (q >> 1) * 16);
    const uint32_t b_lane = (uint32_t)(((q & 1) * 8 + r) * B_ROW_B + (q >> 1) * 16);

    float c[4][4][4];
#pragma unroll
    for (int mi = 0; mi < 4; ++mi)
#pragma unroll
        for (int ni = 0; ni < 4; ++ni)
#pragma unroll
            for (int e = 0; e < 4; ++e) c[mi][ni][e] = 0.0f;

    issue_stage(0);
    issue_stage(1);
    issue_stage(2);

    for (int s = 0; s < 16; ++s) {
        CP_WAIT2();
        __syncthreads();
        issue_stage(s + 3);

        const uint32_t bpu = sb + (s & (NSTAGE - 1)) * BUF_SZ;
#pragma unroll
        for (int kc = 0; kc < 2; ++kc) {
            uint32_t ah[4][4], al[4][4], bhf[4][2], blf[4][2];
#pragma unroll
            for (int mi = 0; mi < 4; ++mi) {
                uint32_t aoff = (uint32_t)((wm * 64 + mi * 16) * A_ROW_B + kc * 32) + a_lane;
                ldsm4(bpu + OFF_AH + aoff, ah[mi]);
                ldsm4(bpu + OFF_AL + aoff, al[mi]);
            }
#pragma unroll
            for (int np = 0; np < 2; ++np) {
                uint32_t boff = (uint32_t)(kc * 16 * B_ROW_B + (wn * 32 + np * 16) * 2) + b_lane;
                uint32_t t[4];
                ldsm4t(bpu + OFF_BH + boff, t);
                bhf[np * 2][0] = t[0]; bhf[np * 2][1] = t[1];
                bhf[np * 2 + 1][0] = t[2]; bhf[np * 2 + 1][1] = t[3];
                ldsm4t(bpu + OFF_BL + boff, t);
                blf[np * 2][0] = t[0]; blf[np * 2][1] = t[1];
                blf[np * 2 + 1][0] = t[2]; blf[np * 2 + 1][1] = t[3];
            }
#pragma unroll
            for (int mi = 0; mi < 4; ++mi)
#pragma unroll
                for (int ni = 0; ni < 4; ++ni)
                    mma16816(c[mi][ni], ah[mi], bhf[ni]);
#pragma unroll
            for (int mi = 0; mi < 4; ++mi)
#pragma unroll
                for (int ni = 0; ni < 4; ++ni)
                    mma16816(c[mi][ni], ah[mi], blf[ni]);
#pragma unroll
            for (int mi = 0; mi < 4; ++mi)
#pragma unroll
                for (int ni = 0; ni < 4; ++ni)
                    mma16816(c[mi][ni], al[mi], bhf[ni]);
        }
    }

    // epilogue
    const int g   = lane >> 2;
    const int tig = lane & 3;
#pragma unroll
    for (int mi = 0; mi < 4; ++mi) {
        const size_t row0 = (size_t)bm * 128 + wm * 64 + mi * 16 + g;
#pragma unroll
        for (int ni = 0; ni < 4; ++ni) {
            const int colg = nb + wn * 32 + ni * 8 + tig * 2;
            float2 bv;
            if (MODE == 0) bv = *(const float2*)(bias + colg);
            else           { bv.x = 0.0f; bv.y = 0.0f; }
            float2 v0, v1;
            v0.x = c[mi][ni][0] + bv.x;  v0.y = c[mi][ni][1] + bv.y;
            v1.x = c[mi][ni][2] + bv.x;  v1.y = c[mi][ni][3] + bv.y;
            *(float2*)(C + row0 * 512 + colg)       = v0;
            *(float2*)(C + (row0 + 8) * 512 + colg) = v1;
        }
    }
}

// ===========================================================================
// Kernel 4a: top-4 partials — each block scans a 512-candidate NB split.
// Key = (sq<<11) | global_j : exact (dist, idx) lexicographic order.
// ===========================================================================
__global__ void __launch_bounds__(128)
topk_part_kernel(const int* __restrict__ ca, const int* __restrict__ cb) {
    __shared__ unsigned sc[512];
    const int b     = blockIdx.y;
    const int split = blockIdx.z;
    const int a     = blockIdx.x * 128 + threadIdx.x;
    const int jbase = split * 512;

    const int* cbb = cb + ((size_t)b * NB_ + jbase) * 3;
    for (int j = threadIdx.x; j < 512; j += 128) {
        int x = cbb[j * 3 + 0];
        int y = cbb[j * 3 + 1];
        int z = cbb[j * 3 + 2];
        sc[j] = (unsigned)(x | (y << 8) | (z << 16));
    }
    __syncthreads();

    const int gi = b * NA_ + a;
    const unsigned ap = (unsigned)(ca[gi * 3 + 0] | (ca[gi * 3 + 1] << 8) |
                                   (ca[gi * 3 + 2] << 16));

    unsigned k0 = 0xFFFFFFFFu, k1 = 0xFFFFFFFFu, k2 = 0xFFFFFFFFu, k3 = 0xFFFFFFFFu;
#pragma unroll 4
    for (int j = 0; j < 512; ++j) {
        unsigned d  = __vabsdiffu4(ap, sc[j]);
        unsigned sq = __dp4a(d, d, 0u);
        unsigned key = (sq << 11) | (unsigned)(jbase + j);
        if (key < k3) {
            k3 = key;
            unsigned t;
            if (k3 < k2) { t = k2; k2 = k3; k3 = t; }
            if (k2 < k1) { t = k1; k1 = k2; k2 = t; }
            if (k1 < k0) { t = k0; k0 = k1; k1 = t; }
        }
    }
    uint4 rr; rr.x = k0; rr.y = k1; rr.z = k2; rr.w = k3;
    g_part[(size_t)gi * 4 + split] = rr;
}

// ===========================================================================
// Kernel 4b: merge 4 partial top-4 lists -> final top-4.
// ===========================================================================
__global__ void __launch_bounds__(256)
topk_merge_kernel() {
    const int gi = blockIdx.x * 256 + threadIdx.x;
    unsigned k0 = 0xFFFFFFFFu, k1 = 0xFFFFFFFFu, k2 = 0xFFFFFFFFu, k3 = 0xFFFFFFFFu;
#pragma unroll
    for (int s = 0; s < 4; ++s) {
        uint4 p = g_part[(size_t)gi * 4 + s];
        unsigned v[4] = {p.x, p.y, p.z, p.w};
#pragma unroll
        for (int e = 0; e < 4; ++e) {
            unsigned key = v[e];
            if (key < k3) {
                k3 = key;
                unsigned t;
                if (k3 < k2) { t = k2; k2 = k3; k3 = t; }
                if (k2 < k1) { t = k1; k1 = k2; k2 = t; }
                if (k1 < k0) { t = k0; k0 = k1; k1 = t; }
            }
        }
    }
    uint4 rr; rr.x = k0; rr.y = k1; rr.z = k2; rr.w = k3;
    *(uint4*)&g_topk[(size_t)gi * 4] = rr;
}

// ===========================================================================
// Kernel 5: combine.
// out[t][0:512] = feats_a[t];  out[t][512:] = sum_k relu(Pa[t]+Pb[idx_k])*w_k
// ===========================================================================
__global__ void __launch_bounds__(128)
combine_kernel(const float* __restrict__ feats_a, float* __restrict__ out) {
    const int token = blockIdx.x;
    const int b     = token >> 11;
    const int tid   = threadIdx.x;

    uint4 keys = *(const uint4*)&g_topk[(size_t)token * 4];
    unsigned ks[4] = {keys.x, keys.y, keys.z, keys.w};
    float w[4];
    int   idx[4];
#pragma unroll
    for (int k = 0; k < 4; ++k) {
        idx[k] = (int)(ks[k] & 2047u);
        float d = sqrtf((float)(ks[k] >> 11)) * (1.0f / 128.0f);
        w[k] = fmaxf(0.5f - d, 0.0f);
    }

    const size_t rowOff = (size_t)token * D_ + tid * 4;
    float4 fa = *(const float4*)(feats_a + rowOff);
    float4 pa = *(const float4*)(g_Pa + rowOff);

    float4 acc; acc.x = acc.y = acc.z = acc.w = 0.0f;
    const size_t baseB = (size_t)b * NB_ * D_;
#pragma unroll
    for (int k = 0; k < 4; ++k) {
        float4 pb = *(const float4*)(g_Pb + baseB + (size_t)idx[k] * D_ + tid * 4);
        acc.x += fmaxf(pa.x + pb.x, 0.0f) * w[k];
        acc.y += fmaxf(pa.y + pb.y, 0.0f) * w[k];
        acc.z += fmaxf(pa.z + pb.z, 0.0f) * w[k];
        acc.w += fmaxf(pa.w + pb.w, 0.0f) * w[k];
    }

    float* orow = out + (size_t)token * (2 * D_);
    *(float4*)(orow + tid * 4)      = fa;
    *(float4*)(orow + D_ + tid * 4) = acc;
}

// ===========================================================================
// Launch. Inputs: feats_a, feats_b, W, bias, coords_a, coords_b
// ===========================================================================
extern "C" void kernel_launch(void* const* d_in, const int* in_sizes, int n_in,
                              void* d_out, int out_size) {
    const float* feats_a = (const float*)d_in[0];
    const float* feats_b = (const float*)d_in[1];
    const float* W       = (const float*)d_in[2];
    const float* bias    = (const float*)d_in[3];
    const int*   ca      = (const int*)d_in[4];
    const int*   cb      = (const int*)d_in[5];
    float*       out     = (float*)d_out;

    static bool attr_done = false;
    if (!attr_done) {
        cudaFuncSetAttribute(mma_gemm<0>, cudaFuncAttributeMaxDynamicSharedMemorySize,
                             GEMM_SMEM);
        cudaFuncSetAttribute(mma_gemm<1>, cudaFuncAttributeMaxDynamicSharedMemorySize,
                             GEMM_SMEM);
        attr_done = true;
    }

    // 1) W split + transpose-free [k][n] layout
    prep_kernel<<<1024, 256>>>(W);

    // 2) Pa = feats_a @ W2 + bias
    conv_kernel<<<M_ * D_ / 4 / 256, 256>>>(feats_a);
    mma_gemm<0><<<dim3(4, 256), 256, GEMM_SMEM>>>(bias);

    // 3) Pb = feats_b @ (W1 - W2)
    conv_kernel<<<M_ * D_ / 4 / 256, 256>>>(feats_b);
    mma_gemm<1><<<dim3(4, 256), 256, GEMM_SMEM>>>(nullptr);

    // 4) top-4: 4-way NB-split partials, then merge
    topk_part_kernel<<<dim3(NA_ / 128, B_, 4), 128>>>(ca, cb);
    topk_merge_kernel<<<M_ / 256, 256>>>();

    // 5) combine + output assembly
    combine_kernel<<<M_, 128>>>(feats_a, out);

    (void)in_sizes; (void)n_in; (void)out_size;
}

// round 5
// speedup vs baseline: 1.2704x; 1.2704x over previous
#include <cuda_runtime.h>
#include <cuda_fp16.h>
#include <cstdint>

// Problem constants
#define B_   16
#define NA_  2048
#define NB_  2048
#define D_   512
#define M_   (B_ * NA_)      // 32768 tokens

// Scratch (device globals: allocation-free per harness rules)
__device__ float    g_Pa[M_ * D_];        // feats_a @ W2 + bias     (64 MB)
__device__ float    g_Pb[M_ * D_];        // feats_b @ (W1 - W2)     (64 MB)
__device__ unsigned g_topk[M_ * 4];       // final packed keys
__device__ uint4    g_part[M_ * 4];       // partial top-4 per NB-split
__device__ __half   g_Bh[2][D_ * D_];     // [mode][k*512+n]  fp16 hi
__device__ __half   g_Bl[2][D_ * D_];     // [mode][k*512+n]  fp16 lo (residual)

// ===========================================================================
// PTX helpers (baseline PTX only — compiles under compute_103)
// ===========================================================================
__device__ __forceinline__ uint32_t smem_u32(const void* p) {
    uint32_t a;
    asm("{ .reg .u64 t; cvta.to.shared.u64 t, %1; cvt.u32.u64 %0, t; }"
        : "=r"(a) : "l"(p));
    return a;
}
__device__ __forceinline__ void ldsm4(uint32_t addr, uint32_t* r) {
    asm volatile("ldmatrix.sync.aligned.m8n8.x4.shared.b16 {%0,%1,%2,%3}, [%4];"
                 : "=r"(r[0]), "=r"(r[1]), "=r"(r[2]), "=r"(r[3]) : "r"(addr));
}
__device__ __forceinline__ void ldsm4t(uint32_t addr, uint32_t* r) {
    asm volatile("ldmatrix.sync.aligned.m8n8.x4.trans.shared.b16 {%0,%1,%2,%3}, [%4];"
                 : "=r"(r[0]), "=r"(r[1]), "=r"(r[2]), "=r"(r[3]) : "r"(addr));
}
__device__ __forceinline__ void mma16816(float* c, const uint32_t* a, const uint32_t* b) {
    asm volatile(
        "mma.sync.aligned.m16n8k16.row.col.f32.f16.f16.f32 "
        "{%0,%1,%2,%3}, {%4,%5,%6,%7}, {%8,%9}, {%0,%1,%2,%3};"
        : "+f"(c[0]), "+f"(c[1]), "+f"(c[2]), "+f"(c[3])
        : "r"(a[0]), "r"(a[1]), "r"(a[2]), "r"(a[3]), "r"(b[0]), "r"(b[1]));
}

// ===========================================================================
// Kernel 1: prep — fp16 hi/lo split of W2 and (W1 - W2), [k][n] layout.
// Bh + Bl reproduces the fp32 weight to ~2^-22.
// ===========================================================================
__global__ void prep_kernel(const float* __restrict__ W) {
    int idx = blockIdx.x * blockDim.x + threadIdx.x;   // k*512 + n
    float w1 = W[idx];
    float w2 = W[idx + 512 * 512];
    float v0 = w2;
    float v1 = w1 - w2;
    __half h0 = __float2half_rn(v0);
    __half l0 = __float2half_rn(v0 - __half2float(h0));
    __half h1 = __float2half_rn(v1);
    __half l1 = __float2half_rn(v1 - __half2float(h1));
    g_Bh[0][idx] = h0;  g_Bl[0][idx] = l0;
    g_Bh[1][idx] = h1;  g_Bl[1][idx] = l1;
}

// ===========================================================================
// Kernel 2: fused 2-pass fp16 tensor-core GEMM (both operands, blockIdx.z).
//   mode 0: g_Pa = feats_a @ W2 + bias      mode 1: g_Pb = feats_b @ (W1-W2)
// CTA 128x128, 8 warps (2x4), warp 64x32, K stage 32, register double-buffer.
// C = fp16(A) @ Bh + fp16(A) @ Bl    (dropped al@B ~ 2^-11 relative)
// ===========================================================================
#define A_ROW_B  80                       // bytes per A smem row (32 fp16 + pad)
#define B_ROW_B  272                      // bytes per B smem row (128 fp16 + pad)
#define A_PART   (128 * A_ROW_B)          // 10240 B
#define B_PART   (32 * B_ROW_B)           // 8704 B
#define OFF_A    0
#define OFF_BHH  A_PART
#define OFF_BLL  (A_PART + B_PART)
#define BUF_SZ   (A_PART + 2 * B_PART)    // 27648 B
#define GEMM_SMEM (2 * BUF_SZ)            // 55296 B

__global__ void __launch_bounds__(256, 1)
mma_gemm(const float* __restrict__ fa, const float* __restrict__ fb,
         const float* __restrict__ bias) {
    extern __shared__ char smem[];
    const uint32_t sb = smem_u32(smem);

    const int tid  = threadIdx.x;
    const int wid  = tid >> 5;
    const int lane = tid & 31;
    const int wm   = wid & 1;
    const int wn   = wid >> 1;
    const int bn   = blockIdx.x;     // 0..3
    const int bm   = blockIdx.y;     // 0..255
    const int mode = blockIdx.z;     // 0..1

    const float*  A  = mode ? fb : fa;
    const __half* Bh = g_Bh[mode];
    const __half* Bl = g_Bl[mode];
    float*        C  = mode ? g_Pb : g_Pa;
    const int nb = bn * 128;
    const float* Ab = A + (size_t)bm * 128 * 512;

    const int arow = tid >> 1;             // 0..127
    const int acb  = (tid & 1) * 16;       // 16 fp32 per thread

    // ldmatrix lane byte offsets (conflict-free: 80B and 272B row strides)
    const int r = lane & 7, q = lane >> 3;
    const uint32_t a_lane = (uint32_t)(((q & 1) * 8 + r) * A_ROW_B + (q >> 1) * 16);
    const uint32_t b_lane = (uint32_t)(((q & 1) * 8 + r) * B_ROW_B + (q >> 1) * 16);

    float c[4][4][4];
#pragma unroll
    for (int mi = 0; mi < 4; ++mi)
#pragma unroll
        for (int ni = 0; ni < 4; ++ni)
#pragma unroll
            for (int e = 0; e < 4; ++e) c[mi][ni][e] = 0.0f;

    auto load_stage = [&](int k0, float4* a4, uint4* bh4, uint4* bl4) {
        const float* ap = Ab + (size_t)arow * 512 + k0 + acb;
#pragma unroll
        for (int i = 0; i < 4; ++i) a4[i] = *(const float4*)(ap + i * 4);
#pragma unroll
        for (int i = 0; i < 2; ++i) {
            int idx = tid * 2 + i;
            int brow = idx >> 4;             // 0..31
            int bcol = (idx & 15) * 8;       // 0..120
            size_t g = (size_t)(k0 + brow) * 512 + nb + bcol;
            bh4[i] = *(const uint4*)(Bh + g);
            bl4[i] = *(const uint4*)(Bl + g);
        }
    };
    auto store_stage = [&](int buf, const float4* a4, const uint4* bh4, const uint4* bl4) {
        char* bp = smem + buf * BUF_SZ;
#pragma unroll
        for (int i = 0; i < 4; ++i) {
            float4 v = a4[i];
            __half2 p0 = __floats2half2_rn(v.x, v.y);
            __half2 p1 = __floats2half2_rn(v.z, v.w);
            uint2 u;
            u.x = *(const uint32_t*)&p0;  u.y = *(const uint32_t*)&p1;
            uint32_t off = (uint32_t)(arow * A_ROW_B + (acb + i * 4) * 2);
            *(uint2*)(bp + OFF_A + off) = u;
        }
#pragma unroll
        for (int i = 0; i < 2; ++i) {
            int idx = tid * 2 + i;
            int brow = idx >> 4;
            int bcol = (idx & 15) * 8;
            uint32_t off = (uint32_t)(brow * B_ROW_B + bcol * 2);
            *(uint4*)(bp + OFF_BHH + off) = bh4[i];
            *(uint4*)(bp + OFF_BLL + off) = bl4[i];
        }
    };

    // prologue
    {
        float4 a4[4]; uint4 bh4[2], bl4[2];
        load_stage(0, a4, bh4, bl4);
        store_stage(0, a4, bh4, bl4);
    }
    __syncthreads();

    for (int s = 0; s < 16; ++s) {
        const int buf = s & 1;
        float4 a4[4]; uint4 bh4[2], bl4[2];
        if (s < 15) load_stage((s + 1) * 32, a4, bh4, bl4);

        const uint32_t bpu = sb + buf * BUF_SZ;
#pragma unroll
        for (int kc = 0; kc < 2; ++kc) {
            uint32_t ah[4][4], bhf[4][2], blf[4][2];
#pragma unroll
            for (int mi = 0; mi < 4; ++mi) {
                uint32_t aoff = (uint32_t)((wm * 64 + mi * 16) * A_ROW_B + kc * 32) + a_lane;
                ldsm4(bpu + OFF_A + aoff, ah[mi]);
            }
#pragma unroll
            for (int np = 0; np < 2; ++np) {
                uint32_t boff = (uint32_t)(kc * 16 * B_ROW_B + (wn * 32 + np * 16) * 2) + b_lane;
                uint32_t t[4];
                ldsm4t(bpu + OFF_BHH + boff, t);
                bhf[np * 2][0] = t[0]; bhf[np * 2][1] = t[1];
                bhf[np * 2 + 1][0] = t[2]; bhf[np * 2 + 1][1] = t[3];
                ldsm4t(bpu + OFF_BLL + boff, t);
                blf[np * 2][0] = t[0]; blf[np * 2][1] = t[1];
                blf[np * 2 + 1][0] = t[2]; blf[np * 2 + 1][1] = t[3];
            }
#pragma unroll
            for (int mi = 0; mi < 4; ++mi)
#pragma unroll
                for (int ni = 0; ni < 4; ++ni)
                    mma16816(c[mi][ni], ah[mi], bhf[ni]);
#pragma unroll
            for (int mi = 0; mi < 4; ++mi)
#pragma unroll
                for (int ni = 0; ni < 4; ++ni)
                    mma16816(c[mi][ni], ah[mi], blf[ni]);
        }

        if (s < 15) {
            store_stage(buf ^ 1, a4, bh4, bl4);
            __syncthreads();
        }
    }

    // epilogue
    const int g   = lane >> 2;
    const int tig = lane & 3;
#pragma unroll
    for (int mi = 0; mi < 4; ++mi) {
        const size_t row0 = (size_t)bm * 128 + wm * 64 + mi * 16 + g;
#pragma unroll
        for (int ni = 0; ni < 4; ++ni) {
            const int colg = nb + wn * 32 + ni * 8 + tig * 2;
            float2 bv;
            if (mode == 0) bv = *(const float2*)(bias + colg);
            else           { bv.x = 0.0f; bv.y = 0.0f; }
            float2 v0, v1;
            v0.x = c[mi][ni][0] + bv.x;  v0.y = c[mi][ni][1] + bv.y;
            v1.x = c[mi][ni][2] + bv.x;  v1.y = c[mi][ni][3] + bv.y;
            *(float2*)(C + row0 * 512 + colg)       = v0;
            *(float2*)(C + (row0 + 8) * 512 + colg) = v1;
        }
    }
}

// ===========================================================================
// Kernel 3a: top-4 partials — each block scans a 512-candidate NB split.
// Key = (sq<<11) | global_j : exact (dist, idx) lexicographic order, matches
// jax top_k tie-break.
// ===========================================================================
__global__ void __launch_bounds__(128)
topk_part_kernel(const int* __restrict__ ca, const int* __restrict__ cb) {
    __shared__ unsigned sc[512];
    const int b     = blockIdx.y;
    const int split = blockIdx.z;
    const int a     = blockIdx.x * 128 + threadIdx.x;
    const int jbase = split * 512;

    const int* cbb = cb + ((size_t)b * NB_ + jbase) * 3;
    for (int j = threadIdx.x; j < 512; j += 128) {
        int x = cbb[j * 3 + 0];
        int y = cbb[j * 3 + 1];
        int z = cbb[j * 3 + 2];
        sc[j] = (unsigned)(x | (y << 8) | (z << 16));
    }
    __syncthreads();

    const int gi = b * NA_ + a;
    const unsigned ap = (unsigned)(ca[gi * 3 + 0] | (ca[gi * 3 + 1] << 8) |
                                   (ca[gi * 3 + 2] << 16));

    unsigned k0 = 0xFFFFFFFFu, k1 = 0xFFFFFFFFu, k2 = 0xFFFFFFFFu, k3 = 0xFFFFFFFFu;
#pragma unroll 4
    for (int j = 0; j < 512; ++j) {
        unsigned d  = __vabsdiffu4(ap, sc[j]);
        unsigned sq = __dp4a(d, d, 0u);                  // exact, <= 48387
        unsigned key = (sq << 11) | (unsigned)(jbase + j);
        if (key < k3) {
            k3 = key;
            unsigned t;
            if (k3 < k2) { t = k2; k2 = k3; k3 = t; }
            if (k2 < k1) { t = k1; k1 = k2; k2 = t; }
            if (k1 < k0) { t = k0; k0 = k1; k1 = t; }
        }
    }
    uint4 rr; rr.x = k0; rr.y = k1; rr.z = k2; rr.w = k3;
    g_part[(size_t)gi * 4 + split] = rr;
}

// ===========================================================================
// Kernel 3b: merge 4 partial top-4 lists -> final top-4.
// ===========================================================================
__global__ void __launch_bounds__(256)
topk_merge_kernel() {
    const int gi = blockIdx.x * 256 + threadIdx.x;
    unsigned k0 = 0xFFFFFFFFu, k1 = 0xFFFFFFFFu, k2 = 0xFFFFFFFFu, k3 = 0xFFFFFFFFu;
#pragma unroll
    for (int s = 0; s < 4; ++s) {
        uint4 p = g_part[(size_t)gi * 4 + s];
        unsigned v[4] = {p.x, p.y, p.z, p.w};
#pragma unroll
        for (int e = 0; e < 4; ++e) {
            unsigned key = v[e];
            if (key < k3) {
                k3 = key;
                unsigned t;
                if (k3 < k2) { t = k2; k2 = k3; k3 = t; }
                if (k2 < k1) { t = k1; k1 = k2; k2 = t; }
                if (k1 < k0) { t = k0; k0 = k1; k1 = t; }
            }
        }
    }
    uint4 rr; rr.x = k0; rr.y = k1; rr.z = k2; rr.w = k3;
    *(uint4*)&g_topk[(size_t)gi * 4] = rr;
}

// ===========================================================================
// Kernel 4: combine.
// out[t][0:512] = feats_a[t];  out[t][512:] = sum_k relu(Pa[t]+Pb[idx_k])*w_k
// ===========================================================================
__global__ void __launch_bounds__(128)
combine_kernel(const float* __restrict__ feats_a, float* __restrict__ out) {
    const int token = blockIdx.x;
    const int b     = token >> 11;
    const int tid   = threadIdx.x;

    uint4 keys = *(const uint4*)&g_topk[(size_t)token * 4];
    unsigned ks[4] = {keys.x, keys.y, keys.z, keys.w};
    float w[4];
    int   idx[4];
#pragma unroll
    for (int k = 0; k < 4; ++k) {
        idx[k] = (int)(ks[k] & 2047u);
        float d = sqrtf((float)(ks[k] >> 11)) * (1.0f / 128.0f);
        w[k] = fmaxf(0.5f - d, 0.0f);
    }

    const size_t rowOff = (size_t)token * D_ + tid * 4;
    float4 fa = *(const float4*)(feats_a + rowOff);
    float4 pa = *(const float4*)(g_Pa + rowOff);

    float4 acc; acc.x = acc.y = acc.z = acc.w = 0.0f;
    const size_t baseB = (size_t)b * NB_ * D_;
#pragma unroll
    for (int k = 0; k < 4; ++k) {
        float4 pb = *(const float4*)(g_Pb + baseB + (size_t)idx[k] * D_ + tid * 4);
        acc.x += fmaxf(pa.x + pb.x, 0.0f) * w[k];
        acc.y += fmaxf(pa.y + pb.y, 0.0f) * w[k];
        acc.z += fmaxf(pa.z + pb.z, 0.0f) * w[k];
        acc.w += fmaxf(pa.w + pb.w, 0.0f) * w[k];
    }

    float* orow = out + (size_t)token * (2 * D_);
    *(float4*)(orow + tid * 4)      = fa;
    *(float4*)(orow + D_ + tid * 4) = acc;
}

// ===========================================================================
// Launch. Inputs: feats_a, feats_b, W, bias, coords_a, coords_b
// ===========================================================================
extern "C" void kernel_launch(void* const* d_in, const int* in_sizes, int n_in,
                              void* d_out, int out_size) {
    const float* feats_a = (const float*)d_in[0];
    const float* feats_b = (const float*)d_in[1];
    const float* W       = (const float*)d_in[2];
    const float* bias    = (const float*)d_in[3];
    const int*   ca      = (const int*)d_in[4];
    const int*   cb      = (const int*)d_in[5];
    float*       out     = (float*)d_out;

    static bool attr_done = false;
    if (!attr_done) {
        cudaFuncSetAttribute(mma_gemm, cudaFuncAttributeMaxDynamicSharedMemorySize,
                             GEMM_SMEM);
        attr_done = true;
    }

    // 1) W split into fp16 hi/lo, [k][n] layout
    prep_kernel<<<1024, 256>>>(W);

    // 2) top-4: 4-way NB-split partials, then merge (independent of GEMM)
    topk_part_kernel<<<dim3(NA_ / 128, B_, 4), 128>>>(ca, cb);
    topk_merge_kernel<<<M_ / 256, 256>>>();

    // 3) fused: Pa = feats_a @ W2 + bias  AND  Pb = feats_b @ (W1 - W2)
    mma_gemm<<<dim3(4, 256, 2), 256, GEMM_SMEM>>>(feats_a, feats_b, bias);

    // 4) combine + output assembly
    combine_kernel<<<M_, 128>>>(feats_a, out);

    (void)in_sizes; (void)n_in; (void)out_size;
}

// round 6
// speedup vs baseline: 1.8214x; 1.4338x over previous
#include <cuda_runtime.h>
#include <cuda_fp16.h>
#include <cstdint>

// Problem constants
#define B_   16
#define NA_  2048
#define NB_  2048
#define D_   512
#define M_   (B_ * NA_)      // 32768 tokens

// Scratch (device globals: allocation-free per harness rules)
__device__ float    g_Pa[M_ * D_];        // feats_a @ W2 + bias     (64 MB)
__device__ float    g_Pb[M_ * D_];        // feats_b @ (W1 - W2)     (64 MB)
__device__ unsigned g_topk[M_ * 4];       // final packed keys
__device__ uint4    g_part[M_ * 4];       // partial top-4 per NB-split
// B in mma.m16n8k16 fragment order: [mode][kblk 0..31][npair 0..31][lane 0..31]
__device__ uint4    g_Bf[2 * 32 * 32 * 32];   // 1 MB

// ===========================================================================
// PTX helpers (baseline PTX only — compiles under compute_103)
// ===========================================================================
__device__ __forceinline__ uint32_t smem_u32(const void* p) {
    uint32_t a;
    asm("{ .reg .u64 t; cvta.to.shared.u64 t, %1; cvt.u32.u64 %0, t; }"
        : "=r"(a) : "l"(p));
    return a;
}
__device__ __forceinline__ void ldsm4(uint32_t addr, uint32_t* r) {
    asm volatile("ldmatrix.sync.aligned.m8n8.x4.shared.b16 {%0,%1,%2,%3}, [%4];"
                 : "=r"(r[0]), "=r"(r[1]), "=r"(r[2]), "=r"(r[3]) : "r"(addr));
}
__device__ __forceinline__ void mma16816(float* c, const uint32_t* a, const uint32_t* b) {
    asm volatile(
        "mma.sync.aligned.m16n8k16.row.col.f32.f16.f16.f32 "
        "{%0,%1,%2,%3}, {%4,%5,%6,%7}, {%8,%9}, {%0,%1,%2,%3};"
        : "+f"(c[0]), "+f"(c[1]), "+f"(c[2]), "+f"(c[3])
        : "r"(a[0]), "r"(a[1]), "r"(a[2]), "r"(a[3]), "r"(b[0]), "r"(b[1]));
}

// ===========================================================================
// Kernel 1: prep — emit B (W2 and W1-W2) in fp16 m16n8k16 B-fragment order.
// B[k][n]; fragment for n8 block: reg0={B[k0][n],B[k0+1][n]},
// reg1={B[k0+8][n],B[k0+9][n]}, k0=(lane%4)*2, n=lane/4.
// uint4 packs two adjacent n8 blocks (one npair = 16 cols).
// ===========================================================================
__global__ void __launch_bounds__(256)
prep_frag_kernel(const float* __restrict__ W) {
    int t = blockIdx.x * blockDim.x + threadIdx.x;   // 0..65535
    int lane  = t & 31;
    int npair = (t >> 5) & 31;
    int kblk  = (t >> 10) & 31;
    int mode  = t >> 15;
    int K0 = kblk * 16 + (lane & 3) * 2;
    int N0 = npair * 16 + (lane >> 2);

    auto val = [&](int k, int n) -> float {
        float w2 = W[(512 + k) * 512 + n];
        return mode ? (W[k * 512 + n] - w2) : w2;
    };
    __half2 x = __floats2half2_rn(val(K0,     N0),     val(K0 + 1, N0));
    __half2 y = __floats2half2_rn(val(K0 + 8, N0),     val(K0 + 9, N0));
    __half2 z = __floats2half2_rn(val(K0,     N0 + 8), val(K0 + 1, N0 + 8));
    __half2 w = __floats2half2_rn(val(K0 + 8, N0 + 8), val(K0 + 9, N0 + 8));
    uint4 u;
    u.x = *(const uint32_t*)&x;  u.y = *(const uint32_t*)&y;
    u.z = *(const uint32_t*)&z;  u.w = *(const uint32_t*)&w;
    g_Bf[t] = u;
}

// ===========================================================================
// Kernel 2: fused single-pass fp16 tensor-core GEMM (mode = blockIdx.z).
//   mode 0: g_Pa = feats_a @ W2 + bias  AND  out[:,0:512] tile = feats_a
//   mode 1: g_Pb = feats_b @ (W1-W2)
// CTA 128x128, 8 warps (2x4), warp 64x32. A fp32->fp16 via smem double
// buffer; B loaded as fragments directly from global (L1/L2 resident).
// ===========================================================================
#define A_ROW_B  80                       // bytes per A smem row (32 fp16 + pad)
#define BUF_SZ   (128 * A_ROW_B)          // 10240 B
#define GEMM_SMEM (2 * BUF_SZ)            // 20480 B (static)

__global__ void __launch_bounds__(256, 2)
mma_gemm(const float* __restrict__ fa, const float* __restrict__ fb,
         const float* __restrict__ bias, float* __restrict__ out) {
    __shared__ __align__(16) char smem[GEMM_SMEM];
    const uint32_t sb = smem_u32(smem);

    const int tid  = threadIdx.x;
    const int wid  = tid >> 5;
    const int lane = tid & 31;
    const int wm   = wid & 1;
    const int wn   = wid >> 1;
    const int bn   = blockIdx.x;     // 0..3
    const int bm   = blockIdx.y;     // 0..255
    const int mode = blockIdx.z;     // 0..1

    const float* A = mode ? fb : fa;
    float*       C = mode ? g_Pb : g_Pa;
    const int nb = bn * 128;
    const float* Ab = A + (size_t)bm * 128 * 512;

    const int arow = tid >> 1;             // 0..127
    const int acb  = (tid & 1) * 16;       // 16 fp32 per thread

    // ldmatrix lane byte offset (conflict-free with 80B row stride)
    const int r = lane & 7, q = lane >> 3;
    const uint32_t a_lane = (uint32_t)(((q & 1) * 8 + r) * A_ROW_B + (q >> 1) * 16);

    // B fragment base for this warp: npair = bn*8 + wn*2
    const uint4* __restrict__ Bf =
        g_Bf + ((size_t)(mode * 32) * 32 + bn * 8 + wn * 2) * 32 + lane;

    float c[4][4][4];
#pragma unroll
    for (int mi = 0; mi < 4; ++mi)
#pragma unroll
        for (int ni = 0; ni < 4; ++ni)
#pragma unroll
            for (int e = 0; e < 4; ++e) c[mi][ni][e] = 0.0f;

    auto load_stage = [&](int k0, float4* a4) {
        const float* ap = Ab + (size_t)arow * 512 + k0 + acb;
#pragma unroll
        for (int i = 0; i < 4; ++i) a4[i] = *(const float4*)(ap + i * 4);
    };
    auto store_stage = [&](int buf, const float4* a4) {
        char* bp = smem + buf * BUF_SZ;
#pragma unroll
        for (int i = 0; i < 4; ++i) {
            float4 v = a4[i];
            __half2 p0 = __floats2half2_rn(v.x, v.y);
            __half2 p1 = __floats2half2_rn(v.z, v.w);
            uint2 u;
            u.x = *(const uint32_t*)&p0;  u.y = *(const uint32_t*)&p1;
            *(uint2*)(bp + arow * A_ROW_B + (acb + i * 4) * 2) = u;
        }
    };

    // prologue
    {
        float4 a4[4];
        load_stage(0, a4);
        store_stage(0, a4);
    }
    __syncthreads();

    for (int s = 0; s < 16; ++s) {
        const int buf = s & 1;
        float4 a4[4];
        if (s < 15) load_stage((s + 1) * 32, a4);

        const uint32_t bpu = sb + buf * BUF_SZ;
#pragma unroll
        for (int kc = 0; kc < 2; ++kc) {
            const int kblk = s * 2 + kc;          // global 16-K block
            uint32_t ah[4][4];
#pragma unroll
            for (int mi = 0; mi < 4; ++mi) {
                uint32_t aoff = (uint32_t)((wm * 64 + mi * 16) * A_ROW_B + kc * 32) + a_lane;
                ldsm4(bpu + aoff, ah[mi]);
            }
            // B fragments: 2 x LDG.128 (L1/L2 resident, broadcast across CTAs)
            uint4 v0 = Bf[(size_t)kblk * 32 * 32];
            uint4 v1 = Bf[(size_t)kblk * 32 * 32 + 32];
            uint32_t bf[4][2];
            bf[0][0] = v0.x;  bf[0][1] = v0.y;
            bf[1][0] = v0.z;  bf[1][1] = v0.w;
            bf[2][0] = v1.x;  bf[2][1] = v1.y;
            bf[3][0] = v1.z;  bf[3][1] = v1.w;
#pragma unroll
            for (int mi = 0; mi < 4; ++mi)
#pragma unroll
                for (int ni = 0; ni < 4; ++ni)
                    mma16816(c[mi][ni], ah[mi], bf[ni]);
        }

        if (s < 15) {
            store_stage(buf ^ 1, a4);
            __syncthreads();
        }
    }

    // epilogue: store C (+bias for mode 0)
    const int g   = lane >> 2;
    const int tig = lane & 3;
#pragma unroll
    for (int mi = 0; mi < 4; ++mi) {
        const size_t row0 = (size_t)bm * 128 + wm * 64 + mi * 16 + g;
#pragma unroll
        for (int ni = 0; ni < 4; ++ni) {
            const int colg = nb + wn * 32 + ni * 8 + tig * 2;
            float2 bv;
            if (mode == 0) bv = *(const float2*)(bias + colg);
            else           { bv.x = 0.0f; bv.y = 0.0f; }
            float2 v0, v1;
            v0.x = c[mi][ni][0] + bv.x;  v0.y = c[mi][ni][1] + bv.y;
            v1.x = c[mi][ni][2] + bv.x;  v1.y = c[mi][ni][3] + bv.y;
            *(float2*)(C + row0 * 512 + colg)       = v0;
            *(float2*)(C + (row0 + 8) * 512 + colg) = v1;
        }
    }

    // mode 0: copy feats_a tile into out[:, 0:512] (GEMM has DRAM headroom)
    if (mode == 0) {
        const int crow = tid >> 1;                 // 0..127
        const int ccol = nb + (tid & 1) * 64;      // 64-col half
        const float* src = fa + ((size_t)bm * 128 + crow) * 512 + ccol;
        float* dst = out + ((size_t)bm * 128 + crow) * 1024 + ccol;
#pragma unroll
        for (int i = 0; i < 16; ++i)
            *(float4*)(dst + i * 4) = *(const float4*)(src + i * 4);
    }
}

// ===========================================================================
// Kernel 3a: top-4 partials — each block scans a 512-candidate NB split.
// Key = (sq<<11) | global_j : exact (dist, idx) lexicographic order.
// ===========================================================================
__global__ void __launch_bounds__(128)
topk_part_kernel(const int* __restrict__ ca, const int* __restrict__ cb) {
    __shared__ unsigned sc[512];
    const int b     = blockIdx.y;
    const int split = blockIdx.z;
    const int a     = blockIdx.x * 128 + threadIdx.x;
    const int jbase = split * 512;

    const int* cbb = cb + ((size_t)b * NB_ + jbase) * 3;
    for (int j = threadIdx.x; j < 512; j += 128) {
        int x = cbb[j * 3 + 0];
        int y = cbb[j * 3 + 1];
        int z = cbb[j * 3 + 2];
        sc[j] = (unsigned)(x | (y << 8) | (z << 16));
    }
    __syncthreads();

    const int gi = b * NA_ + a;
    const unsigned ap = (unsigned)(ca[gi * 3 + 0] | (ca[gi * 3 + 1] << 8) |
                                   (ca[gi * 3 + 2] << 16));

    unsigned k0 = 0xFFFFFFFFu, k1 = 0xFFFFFFFFu, k2 = 0xFFFFFFFFu, k3 = 0xFFFFFFFFu;
#pragma unroll 4
    for (int j = 0; j < 512; ++j) {
        unsigned d  = __vabsdiffu4(ap, sc[j]);
        unsigned sq = __dp4a(d, d, 0u);                  // exact, <= 48387
        unsigned key = (sq << 11) | (unsigned)(jbase + j);
        if (key < k3) {
            k3 = key;
            unsigned t;
            if (k3 < k2) { t = k2; k2 = k3; k3 = t; }
            if (k2 < k1) { t = k1; k1 = k2; k2 = t; }
            if (k1 < k0) { t = k0; k0 = k1; k1 = t; }
        }
    }
    uint4 rr; rr.x = k0; rr.y = k1; rr.z = k2; rr.w = k3;
    g_part[(size_t)gi * 4 + split] = rr;
}

// ===========================================================================
// Kernel 3b: merge 4 partial top-4 lists -> final top-4.
// ===========================================================================
__global__ void __launch_bounds__(256)
topk_merge_kernel() {
    const int gi = blockIdx.x * 256 + threadIdx.x;
    unsigned k0 = 0xFFFFFFFFu, k1 = 0xFFFFFFFFu, k2 = 0xFFFFFFFFu, k3 = 0xFFFFFFFFu;
#pragma unroll
    for (int s = 0; s < 4; ++s) {
        uint4 p = g_part[(size_t)gi * 4 + s];
        unsigned v[4] = {p.x, p.y, p.z, p.w};
#pragma unroll
        for (int e = 0; e < 4; ++e) {
            unsigned key = v[e];
            if (key < k3) {
                k3 = key;
                unsigned t;
                if (k3 < k2) { t = k2; k2 = k3; k3 = t; }
                if (k2 < k1) { t = k1; k1 = k2; k2 = t; }
                if (k1 < k0) { t = k0; k0 = k1; k1 = t; }
            }
        }
    }
    uint4 rr; rr.x = k0; rr.y = k1; rr.z = k2; rr.w = k3;
    *(uint4*)&g_topk[(size_t)gi * 4] = rr;
}

// ===========================================================================
// Kernel 4: combine (fused half only; out[:,0:512] written by GEMM epilogue).
// out[t][512:] = sum_k relu(Pa[t] + Pb[idx_k]) * w_k
// ===========================================================================
__global__ void __launch_bounds__(128)
combine_kernel(float* __restrict__ out) {
    const int token = blockIdx.x;
    const int b     = token >> 11;
    const int tid   = threadIdx.x;

    uint4 keys = *(const uint4*)&g_topk[(size_t)token * 4];
    unsigned ks[4] = {keys.x, keys.y, keys.z, keys.w};
    float w[4];
    int   idx[4];
#pragma unroll
    for (int k = 0; k < 4; ++k) {
        idx[k] = (int)(ks[k] & 2047u);
        float d = sqrtf((float)(ks[k] >> 11)) * (1.0f / 128.0f);
        w[k] = fmaxf(0.5f - d, 0.0f);
    }

    const size_t rowOff = (size_t)token * D_ + tid * 4;
    float4 pa = *(const float4*)(g_Pa + rowOff);

    float4 acc; acc.x = acc.y = acc.z = acc.w = 0.0f;
    const size_t baseB = (size_t)b * NB_ * D_;
#pragma unroll
    for (int k = 0; k < 4; ++k) {
        float4 pb = *(const float4*)(g_Pb + baseB + (size_t)idx[k] * D_ + tid * 4);
        acc.x += fmaxf(pa.x + pb.x, 0.0f) * w[k];
        acc.y += fmaxf(pa.y + pb.y, 0.0f) * w[k];
        acc.z += fmaxf(pa.z + pb.z, 0.0f) * w[k];
        acc.w += fmaxf(pa.w + pb.w, 0.0f) * w[k];
    }

    *(float4*)(out + (size_t)token * 1024 + D_ + tid * 4) = acc;
}

// ===========================================================================
// Launch. Inputs: feats_a, feats_b, W, bias, coords_a, coords_b
// ===========================================================================
extern "C" void kernel_launch(void* const* d_in, const int* in_sizes, int n_in,
                              void* d_out, int out_size) {
    const float* feats_a = (const float*)d_in[0];
    const float* feats_b = (const float*)d_in[1];
    const float* W       = (const float*)d_in[2];
    const float* bias    = (const float*)d_in[3];
    const int*   ca      = (const int*)d_in[4];
    const int*   cb      = (const int*)d_in[5];
    float*       out     = (float*)d_out;

    // 1) W -> fp16 B fragments (both modes)
    prep_frag_kernel<<<256, 256>>>(W);

    // 2) top-4: 4-way NB-split partials, then merge
    topk_part_kernel<<<dim3(NA_ / 128, B_, 4), 128>>>(ca, cb);
    topk_merge_kernel<<<M_ / 256, 256>>>();

    // 3) fused GEMMs (+ feats_a passthrough copy in mode-0 epilogue)
    mma_gemm<<<dim3(4, 256, 2), 256>>>(feats_a, feats_b, bias, out);

    // 4) combine fused half
    combine_kernel<<<M_, 128>>>(out);

    (void)in_sizes; (void)n_in; (void)out_size;
}

// round 7
// speedup vs baseline: 1.8615x; 1.0220x over previous
#include <cuda_runtime.h>
#include <cuda_fp16.h>
#include <cstdint>

// Problem constants
#define B_   16
#define NA_  2048
#define NB_  2048
#define D_   512
#define M_   (B_ * NA_)      // 32768 tokens

// Scratch (device globals: allocation-free per harness rules)
__device__ float    g_Pa[M_ * D_];        // feats_a @ W2 + bias     (64 MB)
__device__ float    g_Pb[M_ * D_];        // feats_b @ (W1 - W2)     (64 MB)
__device__ unsigned g_topk[M_ * 4];       // final packed keys
__device__ uint4    g_part[M_ * 4];       // partial top-4 per NB-split
// B in mma.m16n8k16 fragment order: [mode][kblk 0..31][npair 0..31][lane 0..31]
__device__ uint4    g_Bf[2 * 32 * 32 * 32];   // 1 MB

// ===========================================================================
// PTX helpers (baseline PTX only — compiles under compute_103)
// ===========================================================================
__device__ __forceinline__ uint32_t smem_u32(const void* p) {
    uint32_t a;
    asm("{ .reg .u64 t; cvta.to.shared.u64 t, %1; cvt.u32.u64 %0, t; }"
        : "=r"(a) : "l"(p));
    return a;
}
__device__ __forceinline__ void ldsm4(uint32_t addr, uint32_t* r) {
    asm volatile("ldmatrix.sync.aligned.m8n8.x4.shared.b16 {%0,%1,%2,%3}, [%4];"
                 : "=r"(r[0]), "=r"(r[1]), "=r"(r[2]), "=r"(r[3]) : "r"(addr));
}
__device__ __forceinline__ void mma16816(float* c, const uint32_t* a, const uint32_t* b) {
    asm volatile(
        "mma.sync.aligned.m16n8k16.row.col.f32.f16.f16.f32 "
        "{%0,%1,%2,%3}, {%4,%5,%6,%7}, {%8,%9}, {%0,%1,%2,%3};"
        : "+f"(c[0]), "+f"(c[1]), "+f"(c[2]), "+f"(c[3])
        : "r"(a[0]), "r"(a[1]), "r"(a[2]), "r"(a[3]), "r"(b[0]), "r"(b[1]));
}

// ===========================================================================
// Kernel 1: prep — emit B (W2 and W1-W2) in fp16 m16n8k16 B-fragment order.
// ===========================================================================
__global__ void __launch_bounds__(256)
prep_frag_kernel(const float* __restrict__ W) {
    int t = blockIdx.x * blockDim.x + threadIdx.x;   // 0..65535
    int lane  = t & 31;
    int npair = (t >> 5) & 31;
    int kblk  = (t >> 10) & 31;
    int mode  = t >> 15;
    int K0 = kblk * 16 + (lane & 3) * 2;
    int N0 = npair * 16 + (lane >> 2);

    auto val = [&](int k, int n) -> float {
        float w2 = W[(512 + k) * 512 + n];
        return mode ? (W[k * 512 + n] - w2) : w2;
    };
    __half2 x = __floats2half2_rn(val(K0,     N0),     val(K0 + 1, N0));
    __half2 y = __floats2half2_rn(val(K0 + 8, N0),     val(K0 + 9, N0));
    __half2 z = __floats2half2_rn(val(K0,     N0 + 8), val(K0 + 1, N0 + 8));
    __half2 w = __floats2half2_rn(val(K0 + 8, N0 + 8), val(K0 + 9, N0 + 8));
    uint4 u;
    u.x = *(const uint32_t*)&x;  u.y = *(const uint32_t*)&y;
    u.z = *(const uint32_t*)&z;  u.w = *(const uint32_t*)&w;
    g_Bf[t] = u;
}

// ===========================================================================
// Kernel 2: fused single-pass fp16 GEMM (mode = blockIdx.z).
// CTA 128x256, 8 warps in 2Mx4N, warp tile 64x64 (fragment traffic/MMA -33%).
// A fp32->fp16 via smem double buffer; B fragments LDG'd from global.
//   mode 0: g_Pa = feats_a @ W2 + bias  AND out[:,0:512] tile = feats_a
//   mode 1: g_Pb = feats_b @ (W1-W2)
// ===========================================================================
#define A_ROW_B  80                       // bytes per A smem row (32 fp16 + pad)
#define BUF_SZ   (128 * A_ROW_B)          // 10240 B
#define GEMM_SMEM (2 * BUF_SZ)            // 20480 B (static)

__global__ void __launch_bounds__(256, 1)
mma_gemm(const float* __restrict__ fa, const float* __restrict__ fb,
         const float* __restrict__ bias, float* __restrict__ out) {
    __shared__ __align__(16) char smem[GEMM_SMEM];
    const uint32_t sb = smem_u32(smem);

    const int tid  = threadIdx.x;
    const int wid  = tid >> 5;
    const int lane = tid & 31;
    const int wm   = wid & 1;        // 2 M-slabs of 64
    const int wn   = wid >> 1;       // 4 N-slabs of 64
    const int bn   = blockIdx.x;     // 0..1  (256-col halves)
    const int bm   = blockIdx.y;     // 0..255
    const int mode = blockIdx.z;     // 0..1

    const float* A = mode ? fb : fa;
    float*       C = mode ? g_Pb : g_Pa;
    const int nb = bn * 256;
    const float* Ab = A + (size_t)bm * 128 * 512;

    const int arow = tid >> 1;             // 0..127
    const int acb  = (tid & 1) * 16;       // 16 fp32 per thread

    // ldmatrix lane byte offset (conflict-free with 80B row stride)
    const int r = lane & 7, q = lane >> 3;
    const uint32_t a_lane = (uint32_t)(((q & 1) * 8 + r) * A_ROW_B + (q >> 1) * 16);

    // B fragment base: npair0 = bn*16 + wn*4 ; layout [mode][kblk][npair][lane]
    const uint4* __restrict__ Bf =
        g_Bf + ((size_t)mode * 32 * 32 + (size_t)(bn * 16 + wn * 4)) * 32 + lane;

    float c[4][8][4];
#pragma unroll
    for (int mi = 0; mi < 4; ++mi)
#pragma unroll
        for (int ni = 0; ni < 8; ++ni)
#pragma unroll
            for (int e = 0; e < 4; ++e) c[mi][ni][e] = 0.0f;

    auto load_stage = [&](int k0, float4* a4) {
        const float* ap = Ab + (size_t)arow * 512 + k0 + acb;
#pragma unroll
        for (int i = 0; i < 4; ++i) a4[i] = *(const float4*)(ap + i * 4);
    };
    auto store_stage = [&](int buf, const float4* a4) {
        char* bp = smem + buf * BUF_SZ;
#pragma unroll
        for (int i = 0; i < 4; ++i) {
            float4 v = a4[i];
            __half2 p0 = __floats2half2_rn(v.x, v.y);
            __half2 p1 = __floats2half2_rn(v.z, v.w);
            uint2 u;
            u.x = *(const uint32_t*)&p0;  u.y = *(const uint32_t*)&p1;
            *(uint2*)(bp + arow * A_ROW_B + (acb + i * 4) * 2) = u;
        }
    };

    // prologue
    {
        float4 a4[4];
        load_stage(0, a4);
        store_stage(0, a4);
    }
    __syncthreads();

    for (int s = 0; s < 16; ++s) {
        const int buf = s & 1;
        float4 a4[4];
        if (s < 15) load_stage((s + 1) * 32, a4);

        const uint32_t bpu = sb + buf * BUF_SZ;
#pragma unroll
        for (int kc = 0; kc < 2; ++kc) {
            const int kblk = s * 2 + kc;          // global 16-K block
            uint32_t ah[4][4];
#pragma unroll
            for (int mi = 0; mi < 4; ++mi) {
                uint32_t aoff = (uint32_t)((wm * 64 + mi * 16) * A_ROW_B + kc * 32) + a_lane;
                ldsm4(bpu + aoff, ah[mi]);
            }
            // 4 npairs (64 cols) of B fragments: 4 x LDG.128, L1/L2 broadcast
            uint32_t bf[8][2];
#pragma unroll
            for (int p = 0; p < 4; ++p) {
                uint4 v = Bf[(size_t)kblk * 32 * 32 + p * 32];
                bf[p * 2][0]     = v.x;  bf[p * 2][1]     = v.y;
                bf[p * 2 + 1][0] = v.z;  bf[p * 2 + 1][1] = v.w;
            }
#pragma unroll
            for (int mi = 0; mi < 4; ++mi)
#pragma unroll
                for (int ni = 0; ni < 8; ++ni)
                    mma16816(c[mi][ni], ah[mi], bf[ni]);
        }

        if (s < 15) {
            store_stage(buf ^ 1, a4);
            __syncthreads();
        }
    }

    // epilogue: store C (+bias for mode 0)
    const int g   = lane >> 2;
    const int tig = lane & 3;
#pragma unroll
    for (int mi = 0; mi < 4; ++mi) {
        const size_t row0 = (size_t)bm * 128 + wm * 64 + mi * 16 + g;
#pragma unroll
        for (int ni = 0; ni < 8; ++ni) {
            const int colg = nb + wn * 64 + ni * 8 + tig * 2;
            float2 bv;
            if (mode == 0) bv = *(const float2*)(bias + colg);
            else           { bv.x = 0.0f; bv.y = 0.0f; }
            float2 v0, v1;
            v0.x = c[mi][ni][0] + bv.x;  v0.y = c[mi][ni][1] + bv.y;
            v1.x = c[mi][ni][2] + bv.x;  v1.y = c[mi][ni][3] + bv.y;
            *(float2*)(C + row0 * 512 + colg)       = v0;
            *(float2*)(C + (row0 + 8) * 512 + colg) = v1;
        }
    }

    // mode 0: copy feats_a tile into out[:, 0:512] (DRAM headroom in GEMM)
    if (mode == 0) {
        const int crow = tid >> 1;                 // 0..127
        const int ccol = nb + (tid & 1) * 128;     // 128-col half of 256
        const float* src = fa + ((size_t)bm * 128 + crow) * 512 + ccol;
        float* dst = out + ((size_t)bm * 128 + crow) * 1024 + ccol;
#pragma unroll
        for (int i = 0; i < 32; ++i)
            *(float4*)(dst + i * 4) = *(const float4*)(src + i * 4);
    }
}

// ===========================================================================
// Kernel 3a: top-4 partials — each block scans a 512-candidate NB split.
// Key = (sq<<11) | global_j : exact (dist, idx) lexicographic order.
// ===========================================================================
__global__ void __launch_bounds__(128)
topk_part_kernel(const int* __restrict__ ca, const int* __restrict__ cb) {
    __shared__ unsigned sc[512];
    const int b     = blockIdx.y;
    const int split = blockIdx.z;
    const int a     = blockIdx.x * 128 + threadIdx.x;
    const int jbase = split * 512;

    const int* cbb = cb + ((size_t)b * NB_ + jbase) * 3;
    for (int j = threadIdx.x; j < 512; j += 128) {
        int x = cbb[j * 3 + 0];
        int y = cbb[j * 3 + 1];
        int z = cbb[j * 3 + 2];
        sc[j] = (unsigned)(x | (y << 8) | (z << 16));
    }
    __syncthreads();

    const int gi = b * NA_ + a;
    const unsigned ap = (unsigned)(ca[gi * 3 + 0] | (ca[gi * 3 + 1] << 8) |
                                   (ca[gi * 3 + 2] << 16));

    unsigned k0 = 0xFFFFFFFFu, k1 = 0xFFFFFFFFu, k2 = 0xFFFFFFFFu, k3 = 0xFFFFFFFFu;
#pragma unroll 4
    for (int j = 0; j < 512; ++j) {
        unsigned d  = __vabsdiffu4(ap, sc[j]);
        unsigned sq = __dp4a(d, d, 0u);                  // exact, <= 48387
        unsigned key = (sq << 11) | (unsigned)(jbase + j);
        if (key < k3) {
            k3 = key;
            unsigned t;
            if (k3 < k2) { t = k2; k2 = k3; k3 = t; }
            if (k2 < k1) { t = k1; k1 = k2; k2 = t; }
            if (k1 < k0) { t = k0; k0 = k1; k1 = t; }
        }
    }
    uint4 rr; rr.x = k0; rr.y = k1; rr.z = k2; rr.w = k3;
    g_part[(size_t)gi * 4 + split] = rr;
}

// ===========================================================================
// Kernel 3b: merge 4 partial top-4 lists -> final top-4.
// ===========================================================================
__global__ void __launch_bounds__(256)
topk_merge_kernel() {
    const int gi = blockIdx.x * 256 + threadIdx.x;
    unsigned k0 = 0xFFFFFFFFu, k1 = 0xFFFFFFFFu, k2 = 0xFFFFFFFFu, k3 = 0xFFFFFFFFu;
#pragma unroll
    for (int s = 0; s < 4; ++s) {
        uint4 p = g_part[(size_t)gi * 4 + s];
        unsigned v[4] = {p.x, p.y, p.z, p.w};
#pragma unroll
        for (int e = 0; e < 4; ++e) {
            unsigned key = v[e];
            if (key < k3) {
                k3 = key;
                unsigned t;
                if (k3 < k2) { t = k2; k2 = k3; k3 = t; }
                if (k2 < k1) { t = k1; k1 = k2; k2 = t; }
                if (k1 < k0) { t = k0; k0 = k1; k1 = t; }
            }
        }
    }
    uint4 rr; rr.x = k0; rr.y = k1; rr.z = k2; rr.w = k3;
    *(uint4*)&g_topk[(size_t)gi * 4] = rr;
}

// ===========================================================================
// Kernel 4: combine (fused half only; out[:,0:512] written by GEMM epilogue).
// out[t][512:] = sum_k relu(Pa[t] + Pb[idx_k]) * w_k
// ===========================================================================
__global__ void __launch_bounds__(128)
combine_kernel(float* __restrict__ out) {
    const int token = blockIdx.x;
    const int b     = token >> 11;
    const int tid   = threadIdx.x;

    uint4 keys = *(const uint4*)&g_topk[(size_t)token * 4];
    unsigned ks[4] = {keys.x, keys.y, keys.z, keys.w};
    float w[4];
    int   idx[4];
#pragma unroll
    for (int k = 0; k < 4; ++k) {
        idx[k] = (int)(ks[k] & 2047u);
        float d = sqrtf((float)(ks[k] >> 11)) * (1.0f / 128.0f);
        w[k] = fmaxf(0.5f - d, 0.0f);
    }

    const size_t rowOff = (size_t)token * D_ + tid * 4;
    float4 pa = *(const float4*)(g_Pa + rowOff);

    float4 acc; acc.x = acc.y = acc.z = acc.w = 0.0f;
    const size_t baseB = (size_t)b * NB_ * D_;
#pragma unroll
    for (int k = 0; k < 4; ++k) {
        float4 pb = *(const float4*)(g_Pb + baseB + (size_t)idx[k] * D_ + tid * 4);
        acc.x += fmaxf(pa.x + pb.x, 0.0f) * w[k];
        acc.y += fmaxf(pa.y + pb.y, 0.0f) * w[k];
        acc.z += fmaxf(pa.z + pb.z, 0.0f) * w[k];
        acc.w += fmaxf(pa.w + pb.w, 0.0f) * w[k];
    }

    *(float4*)(out + (size_t)token * 1024 + D_ + tid * 4) = acc;
}

// ===========================================================================
// Launch. Inputs: feats_a, feats_b, W, bias, coords_a, coords_b
// ===========================================================================
extern "C" void kernel_launch(void* const* d_in, const int* in_sizes, int n_in,
                              void* d_out, int out_size) {
    const float* feats_a = (const float*)d_in[0];
    const float* feats_b = (const float*)d_in[1];
    const float* W       = (const float*)d_in[2];
    const float* bias    = (const float*)d_in[3];
    const int*   ca      = (const int*)d_in[4];
    const int*   cb      = (const int*)d_in[5];
    float*       out     = (float*)d_out;

    // 1) W -> fp16 B fragments (both modes)
    prep_frag_kernel<<<256, 256>>>(W);

    // 2) top-4: 4-way NB-split partials, then merge
    topk_part_kernel<<<dim3(NA_ / 128, B_, 4), 128>>>(ca, cb);
    topk_merge_kernel<<<M_ / 256, 256>>>();

    // 3) fused GEMMs (+ feats_a passthrough copy in mode-0 epilogue)
    mma_gemm<<<dim3(2, 256, 2), 256>>>(feats_a, feats_b, bias, out);

    // 4) combine fused half
    combine_kernel<<<M_, 128>>>(out);

    (void)in_sizes; (void)n_in; (void)out_size;
}